// round 11
// baseline (speedup 1.0000x reference)
#include <cuda_runtime.h>
#include <cstdint>

// Problem constants
#define NN   512
#define NIN  6
#define NOUT 2
#define TS   1200
#define NB   128
#define TB   (TS * NB)          // 153600

// Decomposition: 16 batch-groups x (cluster of 8 n-slice CTAs) = 128 CTAs
#define NSL     8               // n-slices (cluster size)
#define ROWS    64              // rows of W_rec per CTA
#define NBG     16              // batch groups
#define BG      8               // batch per group
#define THREADS 512             // 16 warps -> 4 per SMSP (was 2)
#define NSEG    16              // k-segments (one per warp, 32 k each)
#define BP      12              // partials row pad (floats, mult of 4 for STS.128)

#define F_SSH   ((NN + NIN + 2) * BG)   // 4160: 512 state rows + 6 input rows + pad
#define F_PART  (NSEG * ROWS * BP)      // 12288
#define F_MBAR  4                       // 2 x 8-byte mbarriers
#define SMEM_FLOATS (F_SSH + F_PART + F_MBAR)
#define SMEM_BYTES  (SMEM_FLOATS * 4)   // 65808 B

#define MBAR_ARRIVALS NSL               // ONE aggregated arrive per source CTA

// Ping-pong state exchange buffer (per batch-group), lives in L2.
__device__ float g_S[2][NBG][NN][BG];

typedef unsigned long long ull;

__device__ __forceinline__ ull pack2(float x) {
    ull r;
    unsigned int v = __float_as_uint(x);
    asm("mov.b64 %0, {%1, %1};" : "=l"(r) : "r"(v));
    return r;
}
__device__ __forceinline__ void fma2(ull& d, ull a, ull b) {
    asm("fma.rn.f32x2 %0, %1, %2, %0;" : "+l"(d) : "l"(a), "l"(b));
}
__device__ __forceinline__ void unpack2(ull v, float& lo, float& hi) {
    unsigned int l, h;
    asm("mov.b64 {%0, %1}, %2;" : "=r"(l), "=r"(h) : "l"(v));
    lo = __uint_as_float(l);
    hi = __uint_as_float(h);
}
__device__ __forceinline__ float tanh_fast(float x) {
    float r;
    asm("tanh.approx.f32 %0, %1;" : "=f"(r) : "f"(x));
    return r;
}
__device__ __forceinline__ uint32_t smem_u32(const void* p) {
    uint32_t a;
    asm("{ .reg .u64 t; cvta.to.shared.u64 t, %1; cvt.u32.u64 %0, t; }"
        : "=r"(a) : "l"(p));
    return a;
}
__device__ __forceinline__ void mbar_init(uint32_t addr, uint32_t cnt) {
    asm volatile("mbarrier.init.shared.b64 [%0], %1;" :: "r"(addr), "r"(cnt) : "memory");
}
__device__ __forceinline__ void fence_cluster_() {
    asm volatile("fence.acq_rel.cluster;" ::: "memory");
}
__device__ __forceinline__ void mbar_arrive_rank(uint32_t addr, uint32_t rank) {
    asm volatile(
        "{\n\t"
        ".reg .b32 ra;\n\t"
        "mapa.shared::cluster.u32 ra, %0, %1;\n\t"
        "mbarrier.arrive.shared::cluster.b64 _, [ra];\n\t"
        "}"
        :: "r"(addr), "r"(rank) : "memory");
}
__device__ __forceinline__ void mbar_wait_cluster(uint32_t mbar, uint32_t par) {
    uint32_t done;
    asm volatile(
        "{\n\t"
        ".reg .pred p;\n\t"
        "mbarrier.try_wait.parity.acquire.cluster.shared::cta.b64 p, [%1], %2;\n\t"
        "selp.b32 %0, 1, 0, p;\n\t"
        "}"
        : "=r"(done) : "r"(mbar), "r"(par) : "memory");
    if (!done) {
        asm volatile(
            "{\n\t"
            ".reg .pred P1;\n\t"
            "WL_%=:\n\t"
            "mbarrier.try_wait.parity.acquire.cluster.shared::cta.b64 P1, [%0], %1, 0x989680;\n\t"
            "@P1 bra.uni WD_%=;\n\t"
            "bra.uni WL_%=;\n\t"
            "WD_%=:\n\t"
            "}"
            :: "r"(mbar), "r"(par) : "memory");
    }
}
__device__ __forceinline__ void cluster_arrive_() {
    asm volatile("barrier.cluster.arrive.aligned;" ::: "memory");
}
__device__ __forceinline__ void cluster_wait_() {
    asm volatile("barrier.cluster.wait.aligned;" ::: "memory");
}

// One FFMA2 quad: 1 weight value against 8 batches (4 f32x2 pairs)
#define QFMA(ar, wv, sA, sB)                 \
    do {                                      \
        ull _w = pack2(wv);                   \
        fma2(ar##0, _w, sA.x);                \
        fma2(ar##1, _w, sA.y);                \
        fma2(ar##2, _w, sB.x);                \
        fma2(ar##3, _w, sB.y);                \
    } while (0)

extern "C" __global__ void __cluster_dims__(NSL, 1, 1) __launch_bounds__(THREADS, 1)
rnn_step_kernel(const float* __restrict__ u,
                const float* __restrict__ Wrec,
                const float* __restrict__ Winp,
                const float* __restrict__ Wout,
                const float* __restrict__ y_init,
                const float* __restrict__ rnoise,
                const float* __restrict__ inoise,
                float* __restrict__ states,
                float* __restrict__ outs)
{
    extern __shared__ float sm[];
    float* s_sh = sm;                // [520][8] rows 0..511 state, 512..517 = u+inoise
    float* part = s_sh + F_SSH;      // [16 seg][64 n][12]
    const uint32_t mbar0 = smem_u32(part + F_PART);
    const uint32_t mbar1 = mbar0 + 8;

    const int tid  = threadIdx.x;
    const int ns   = blockIdx.x;     // cluster rank / n-slice
    const int bg   = blockIdx.y;     // batch group
    const int n0   = ns * ROWS;
    const int b0   = bg * BG;
    const int lane = tid & 31;
    const int wid  = tid >> 5;       // 0..15 = k-segment (32 k's each)
    const int kb   = wid * 32;       // this warp's k base

    const int r0 = lane;             // local rows: lane, lane+32
    const int r1 = lane + 32;

    // ---- W_rec slice into registers: 2 rows x 32 k = 16 float4 ----
    float4 wr0[8], wr1[8];
    {
        const float* p0 = Wrec + (size_t)(n0 + r0) * NN + kb;
        const float* p1 = Wrec + (size_t)(n0 + r1) * NN + kb;
        #pragma unroll
        for (int q = 0; q < 8; ++q) {
            wr0[q] = *(const float4*)(p0 + 4 * q);
            wr1[q] = *(const float4*)(p1 + 4 * q);
        }
    }
    // Input-term weights (k-row 512+wid), only warps 0..5 active
    float wi0 = 0.f, wi1 = 0.f;
    if (wid < NIN) {
        wi0 = Winp[(size_t)(n0 + r0) * NIN + wid];
        wi1 = Winp[(size_t)(n0 + r1) * NIN + wid];
    }

    // Reducer output assignment (1 output per thread)
    const int n_r = tid >> 3;             // 0..63
    const int b_r = tid & 7;
    const float woa = Wout[n0 + n_r];          // output 0 weight
    const float wob = Wout[NN + n0 + n_r];     // output 1 weight

    // x loader assignment (threads 0..47)
    const bool xload = (tid < NIN * BG);
    const int  xi = tid >> 3, xb = tid & 7;

    // ---- mbarrier init (before cluster sync so peers can't arrive early) ----
    if (tid == 0) {
        mbar_init(mbar0, MBAR_ARRIVALS);
        mbar_init(mbar1, MBAR_ARRIVALS);
    }

    // ---- Init state buffer + states[:,0,:] + own rows of s_sh ----
    {
        int n = tid >> 3;               // 0..63
        int b = tid & 7;
        float v = y_init[n0 + n];
        g_S[0][bg][n0 + n][b] = v;
        s_sh[(n0 + n) * BG + b] = v;    // own slice seeded locally (stage skips it)
        states[(size_t)(n0 + n) * TB + b0 + b] = v;
    }
    // ---- rank 0 zeroes this batch-group's output slab ----
    if (ns == 0) {
        for (int idx = tid; idx < NOUT * TS * BG; idx += THREADS) {
            int o   = idx / (TS * BG);          // 0 or 1 (stride 9600)
            int rem = idx - o * TS * BG;
            int t = rem >> 3;
            int b = rem & 7;
            outs[(size_t)o * TB + (size_t)t * NB + b0 + b] = 0.f;
        }
    }
    __syncthreads();
    cluster_arrive_();

    // ---- Prefetch t=0 streamed operands ----
    float x_v = 0.f, rn0;
    if (xload) {
        size_t off = (size_t)xi * TB + b0 + xb;
        x_v = __ldcs(u + off) + __ldcs(inoise + off);
    }
    rn0 = __ldcs(rnoise + (size_t)(n0 + n_r) * TB + b0 + b_r);

    cluster_wait_();   // g_S init + out zero + all mbar inits visible cluster-wide

    // ---- t = 0 outputs: Wout @ s0 ----
    {
        float sv = y_init[n0 + n_r];
        float v0 = woa * sv;
        float v1 = wob * sv;
        v0 += __shfl_xor_sync(0xffffffffu, v0, 8);
        v0 += __shfl_xor_sync(0xffffffffu, v0, 16);
        v1 += __shfl_xor_sync(0xffffffffu, v1, 8);
        v1 += __shfl_xor_sync(0xffffffffu, v1, 16);
        if (lane < 8) {
            atomicAdd(outs + b0 + lane, v0);
            atomicAdd(outs + TB + b0 + lane, v1);
        }
    }

    const float* sbase = s_sh + kb * BG;
    const float* sext  = s_sh + (NN + wid) * BG;

    int ph0 = 0, ph1 = 0;   // per-buffer wait parities

    for (int t = 0; t < TS - 1; ++t) {
        // ---- 1. stage remote slices (14KB) from L2; own slice already local ----
        const float4* Sp = (const float4*)(&g_S[t & 1][bg][0][0]);
        float4* s4 = (float4*)s_sh;
        #pragma unroll
        for (int j = 0; j < 2; ++j) {
            int idx = tid + j * 512;        // 0..1023 float4s; slice = idx>>7
            if ((idx >> 7) != ns)
                s4[idx] = __ldcg(Sp + idx);
        }
        if (xload) s_sh[(NN + xi) * BG + xb] = x_v;
        __syncthreads();

        // ---- 2. GEMM partials: 32 k's (regs W) x 2 rows x 8 batches ----
        ull a00 = 0, a01 = 0, a02 = 0, a03 = 0;   // row lane
        ull a10 = 0, a11 = 0, a12 = 0, a13 = 0;   // row lane+32
        {
            const float* sp = sbase;
            #pragma unroll
            for (int q = 0; q < 8; ++q) {
                float4 w0q = wr0[q], w1q = wr1[q];
                #pragma unroll
                for (int c = 0; c < 4; ++c) {
                    ulonglong2 sA = *(const ulonglong2*)(sp);      // b0..b3
                    ulonglong2 sB = *(const ulonglong2*)(sp + 4);  // b4..b7
                    float w0v = (c == 0) ? w0q.x : (c == 1) ? w0q.y : (c == 2) ? w0q.z : w0q.w;
                    float w1v = (c == 0) ? w1q.x : (c == 1) ? w1q.y : (c == 2) ? w1q.z : w1q.w;
                    QFMA(a0, w0v, sA, sB);
                    QFMA(a1, w1v, sA, sB);
                    sp += BG;
                }
            }
            if (wid < NIN) {   // fold input term: one extra k-row (512+wid)
                ulonglong2 sA = *(const ulonglong2*)(sext);
                ulonglong2 sB = *(const ulonglong2*)(sext + 4);
                QFMA(a0, wi0, sA, sB);
                QFMA(a1, wi1, sA, sB);
            }
        }
        // ---- 3. store partials: per row, 8 floats as 2x STS.128 ----
        {
            float4 q;
            float* pb = part + (wid * ROWS) * BP;
            unpack2(a00, q.x, q.y); unpack2(a01, q.z, q.w);
            *(float4*)(pb + r0 * BP) = q;
            unpack2(a02, q.x, q.y); unpack2(a03, q.z, q.w);
            *(float4*)(pb + r0 * BP + 4) = q;
            unpack2(a10, q.x, q.y); unpack2(a11, q.z, q.w);
            *(float4*)(pb + r1 * BP) = q;
            unpack2(a12, q.x, q.y); unpack2(a13, q.z, q.w);
            *(float4*)(pb + r1 * BP + 4) = q;
        }
        __syncthreads();

        // ---- 4. reduce 16 partials, tanh, state update (1 output/thread) ----
        float nsv;
        {
            float pre = 0.f;
            #pragma unroll
            for (int sp = 0; sp < NSEG; ++sp)
                pre += part[(sp * ROWS + n_r) * BP + b_r];
            float s0 = s_sh[(n0 + n_r) * BG + b_r];
            nsv = 0.9f * s0 + 0.1f * (tanh_fast(pre) + rn0);
            float* Sn = &g_S[(t + 1) & 1][bg][0][0];
            Sn[(n0 + n_r) * BG + b_r] = nsv;        // remote CTAs read via L2
            s_sh[(n0 + n_r) * BG + b_r] = nsv;      // own slice stays local
        }

        // ---- 5. aggregated signal: 1 arrive per source CTA per rank ----
        const uint32_t mb = ((t + 1) & 1) ? mbar1 : mbar0;
        __syncthreads();                    // all g_S STGs issued before fence
        if (tid < NSL) {
            fence_cluster_();               // cluster-visible release of g_S writes
            mbar_arrive_rank(mb, tid);      // 8 parallel arrives, one per rank
        }

        // ---- 6. off-chain work: states STG, outs RED, next prefetch ----
        {
            size_t so = (size_t)(t + 1) * NB + b0 + b_r;
            states[(size_t)(n0 + n_r) * TB + so] = nsv;

            float v0 = woa * nsv;
            float v1 = wob * nsv;
            v0 += __shfl_xor_sync(0xffffffffu, v0, 8);
            v0 += __shfl_xor_sync(0xffffffffu, v0, 16);
            v1 += __shfl_xor_sync(0xffffffffu, v1, 8);
            v1 += __shfl_xor_sync(0xffffffffu, v1, 16);
            if (lane < 8) {
                size_t oc = (size_t)(t + 1) * NB + b0 + lane;
                atomicAdd(outs + oc, v0);
                atomicAdd(outs + TB + oc, v1);
            }
        }
        if (t + 1 < TS - 1) {
            size_t toff = (size_t)(t + 1) * NB + b0;
            if (xload) {
                size_t off = (size_t)xi * TB + toff + xb;
                x_v = __ldcs(u + off) + __ldcs(inoise + off);
            }
            rn0 = __ldcs(rnoise + (size_t)(n0 + n_r) * TB + toff + b_r);
        }

        // ---- 7. wait for the cluster-wide exchange of step t+1 ----
        if ((t + 1) & 1) {
            mbar_wait_cluster(mbar1, ph1);
            ph1 ^= 1;
        } else {
            mbar_wait_cluster(mbar0, ph0);
            ph0 ^= 1;
        }
    }
}

extern "C" void kernel_launch(void* const* d_in, const int* in_sizes, int n_in,
                              void* d_out, int out_size)
{
    const float* u      = (const float*)d_in[0];
    const float* Wrec   = (const float*)d_in[1];
    const float* Winp   = (const float*)d_in[2];
    const float* Wout   = (const float*)d_in[3];
    const float* y_init = (const float*)d_in[4];
    const float* rnoise = (const float*)d_in[5];
    const float* inoise = (const float*)d_in[6];

    float* states = (float*)d_out;
    float* outs   = states + (size_t)NN * TB;

    cudaFuncSetAttribute(rnn_step_kernel,
                         cudaFuncAttributeMaxDynamicSharedMemorySize, SMEM_BYTES);

    dim3 grid(NSL, NBG, 1);
    rnn_step_kernel<<<grid, THREADS, SMEM_BYTES>>>(u, Wrec, Winp, Wout, y_init,
                                                   rnoise, inoise, states, outs);
}

// round 12
// speedup vs baseline: 1.1642x; 1.1642x over previous
#include <cuda_runtime.h>
#include <cstdint>

// Problem constants
#define NN   512
#define NIN  6
#define NOUT 2
#define TS   1200
#define NB   128
#define TB   (TS * NB)          // 153600

// Decomposition: 16 batch-groups x (cluster of 8 n-slice CTAs) = 128 CTAs
#define NSL     8               // n-slices (cluster size)
#define ROWS    64              // rows of W_rec per CTA
#define NBG     16              // batch groups
#define BG      8               // batch per group
#define THREADS 256
#define NSEG    16              // k-segments (8 warps x 2 half-warps)
#define BP      12              // partials row pad (floats, mult of 4 for STS.128)

#define F_BUF   ((NN + NIN + 2) * BG)   // 4160 floats per state buffer
#define BUF_BYTES (F_BUF * 4)           // 16640
#define F_PART  (NSEG * ROWS * BP)      // 12288
#define F_MBAR  4                       // 2 x 8-byte mbarriers
#define SMEM_FLOATS (2 * F_BUF + F_PART + F_MBAR)
#define SMEM_BYTES  (SMEM_FLOATS * 4)   // 83104 B

// tx bytes per exchange phase: 512 rows x 8 b x 4B (state, as 2048 b64 msgs)
// + 6 x 8 x 4B (input rows, b32 self-msgs)
#define TXB (NN * BG * 4 + NIN * BG * 4)   // 16576

typedef unsigned long long ull;

__device__ __forceinline__ ull pack2(float x) {
    ull r;
    unsigned int v = __float_as_uint(x);
    asm("mov.b64 %0, {%1, %1};" : "=l"(r) : "r"(v));
    return r;
}
__device__ __forceinline__ ull packpair(float lo, float hi) {
    ull r;
    asm("mov.b64 %0, {%1, %2};" : "=l"(r) : "f"(lo), "f"(hi));
    return r;
}
__device__ __forceinline__ void fma2(ull& d, ull a, ull b) {
    asm("fma.rn.f32x2 %0, %1, %2, %0;" : "+l"(d) : "l"(a), "l"(b));
}
__device__ __forceinline__ void unpack2(ull v, float& lo, float& hi) {
    unsigned int l, h;
    asm("mov.b64 {%0, %1}, %2;" : "=r"(l), "=r"(h) : "l"(v));
    lo = __uint_as_float(l);
    hi = __uint_as_float(h);
}
__device__ __forceinline__ float tanh_fast(float x) {
    float r;
    asm("tanh.approx.f32 %0, %1;" : "=f"(r) : "f"(x));
    return r;
}
__device__ __forceinline__ uint32_t smem_u32(const void* p) {
    uint32_t a;
    asm("{ .reg .u64 t; cvta.to.shared.u64 t, %1; cvt.u32.u64 %0, t; }"
        : "=r"(a) : "l"(p));
    return a;
}
__device__ __forceinline__ uint32_t mapa_rank(uint32_t addr, uint32_t rank) {
    uint32_t r;
    asm("mapa.shared::cluster.u32 %0, %1, %2;" : "=r"(r) : "r"(addr), "r"(rank));
    return r;
}
__device__ __forceinline__ void mbar_init(uint32_t addr, uint32_t cnt) {
    asm volatile("mbarrier.init.shared.b64 [%0], %1;" :: "r"(addr), "r"(cnt) : "memory");
}
__device__ __forceinline__ void mbar_expect_tx(uint32_t addr, uint32_t bytes) {
    asm volatile("mbarrier.arrive.expect_tx.shared.b64 _, [%0], %1;"
                 :: "r"(addr), "r"(bytes) : "memory");
}
__device__ __forceinline__ void st_async_b64(uint32_t daddr, ull v, uint32_t mbar) {
    asm volatile("st.async.shared::cluster.mbarrier::complete_tx::bytes.b64 [%0], %1, [%2];"
                 :: "r"(daddr), "l"(v), "r"(mbar) : "memory");
}
__device__ __forceinline__ void st_async_b32(uint32_t daddr, float v, uint32_t mbar) {
    asm volatile("st.async.shared::cluster.mbarrier::complete_tx::bytes.b32 [%0], %1, [%2];"
                 :: "r"(daddr), "f"(v), "r"(mbar) : "memory");
}
__device__ __forceinline__ void mbar_wait_cluster(uint32_t mbar, uint32_t par) {
    uint32_t done;
    asm volatile(
        "{\n\t"
        ".reg .pred p;\n\t"
        "mbarrier.try_wait.parity.acquire.cluster.shared::cta.b64 p, [%1], %2;\n\t"
        "selp.b32 %0, 1, 0, p;\n\t"
        "}"
        : "=r"(done) : "r"(mbar), "r"(par) : "memory");
    if (!done) {
        asm volatile(
            "{\n\t"
            ".reg .pred P1;\n\t"
            "WL_%=:\n\t"
            "mbarrier.try_wait.parity.acquire.cluster.shared::cta.b64 P1, [%0], %1, 0x989680;\n\t"
            "@P1 bra.uni WD_%=;\n\t"
            "bra.uni WL_%=;\n\t"
            "WD_%=:\n\t"
            "}"
            :: "r"(mbar), "r"(par) : "memory");
    }
}
__device__ __forceinline__ void cluster_arrive_() {
    asm volatile("barrier.cluster.arrive.aligned;" ::: "memory");
}
__device__ __forceinline__ void cluster_wait_() {
    asm volatile("barrier.cluster.wait.aligned;" ::: "memory");
}

#define QFMA(ar, wv, sA, sB)                 \
    do {                                      \
        ull _w = pack2(wv);                   \
        fma2(ar##0, _w, sA.x);                \
        fma2(ar##1, _w, sA.y);                \
        fma2(ar##2, _w, sB.x);                \
        fma2(ar##3, _w, sB.y);                \
    } while (0)

extern "C" __global__ void __cluster_dims__(NSL, 1, 1) __launch_bounds__(THREADS, 1)
rnn_step_kernel(const float* __restrict__ u,
                const float* __restrict__ Wrec,
                const float* __restrict__ Winp,
                const float* __restrict__ Wout,
                const float* __restrict__ y_init,
                const float* __restrict__ rnoise,
                const float* __restrict__ inoise,
                float* __restrict__ states,
                float* __restrict__ outs)
{
    extern __shared__ float sm[];
    // sm: buf0 [520][8] | buf1 [520][8] | part [16][64][12] | 2 mbars
    float* part = sm + 2 * F_BUF;
    const uint32_t bufbase = smem_u32(sm);
    const uint32_t mbarbase = smem_u32(part + F_PART);

    const int tid  = threadIdx.x;
    const int ns   = blockIdx.x;     // cluster rank / n-slice
    const int bg   = blockIdx.y;     // batch group
    const int n0   = ns * ROWS;
    const int b0   = bg * BG;
    const int lane = tid & 31;
    const int wid  = tid >> 5;       // 0..7
    const int g    = lane & 15;      // row group: rows {2g,2g+1,2g+32,2g+33}
    const int h    = lane >> 4;      // k half within warp's 64-k segment
    const int seg  = wid * 2 + h;    // 0..15
    const int kb   = wid * 64 + h * 32;

    const int r0 = 2 * g, r1 = 2 * g + 1, r2 = 2 * g + 32, r3 = 2 * g + 33;

    // ---- peer addresses (compile-time-indexed arrays stay in regs) ----
    uint32_t pbuf[NSL], pmbar[NSL];
    #pragma unroll
    for (int r = 0; r < NSL; ++r) {
        pbuf[r]  = mapa_rank(bufbase, r);
        pmbar[r] = mapa_rank(mbarbase, r);
    }
    const uint32_t pbuf_self  = mapa_rank(bufbase, ns);
    const uint32_t pmbar_self = mapa_rank(mbarbase, ns);

    // ---- W_rec slice into registers: 4 rows x 32 k = 32 float4 ----
    float4 wr0[8], wr1[8], wr2[8], wr3[8];
    {
        const float* p0 = Wrec + (size_t)(n0 + r0) * NN + kb;
        const float* p1 = Wrec + (size_t)(n0 + r1) * NN + kb;
        const float* p2 = Wrec + (size_t)(n0 + r2) * NN + kb;
        const float* p3 = Wrec + (size_t)(n0 + r3) * NN + kb;
        #pragma unroll
        for (int q = 0; q < 8; ++q) {
            wr0[q] = *(const float4*)(p0 + 4 * q);
            wr1[q] = *(const float4*)(p1 + 4 * q);
            wr2[q] = *(const float4*)(p2 + 4 * q);
            wr3[q] = *(const float4*)(p3 + 4 * q);
        }
    }
    float wi0 = 0.f, wi1 = 0.f, wi2 = 0.f, wi3 = 0.f;
    if (seg < NIN) {
        wi0 = Winp[(size_t)(n0 + r0) * NIN + seg];
        wi1 = Winp[(size_t)(n0 + r1) * NIN + seg];
        wi2 = Winp[(size_t)(n0 + r2) * NIN + seg];
        wi3 = Winp[(size_t)(n0 + r3) * NIN + seg];
    }

    // Reducer output assignments (2 outputs per thread)
    const int n_r0 = tid >> 3;            // 0..31
    const int n_r1 = (tid + 256) >> 3;    // 32..63
    const int b_r  = tid & 7;
    const float wo0a = Wout[n0 + n_r0];
    const float wo0b = Wout[n0 + n_r1];
    const float wo1a = Wout[NN + n0 + n_r0];
    const float wo1b = Wout[NN + n0 + n_r1];

    // emit row/col for b64 pair messages (even lane sends row n_r0's pair,
    // odd lane sends row n_r1's pair)
    const bool evenl = (lane & 1) == 0;
    const int emit_row = evenl ? (n0 + n_r0) : (n0 + n_r1);
    const int emit_b   = evenl ? b_r : (b_r ^ 1);
    const uint32_t emit_off = (uint32_t)(emit_row * BG + emit_b) * 4;

    // x loader assignment (threads 0..47)
    const bool xload = (tid < NIN * BG);
    const int  xi = tid >> 3, xb = tid & 7;
    const uint32_t x_off = (uint32_t)((NN + xi) * BG + xb) * 4;

    // ---- mbarrier init; count=1 (thread0's expect_tx arrive per phase) ----
    if (tid == 0) {
        mbar_init(mbarbase, 1);
        mbar_init(mbarbase + 8, 1);
    }

    // ---- Seed buf0 with full y_init state (every CTA), x(0), states/outs ----
    for (int idx = tid; idx < NN * BG; idx += THREADS)
        sm[idx] = y_init[idx >> 3];
    if (xload) {
        size_t off = (size_t)xi * TB + b0 + xb;
        sm[(NN + xi) * BG + xb] = __ldcs(u + off) + __ldcs(inoise + off);
    }
    {   // states[:,0,:] own slice
        int n = tid >> 3, b = tid & 7;
        if (tid < ROWS * BG)
            ;   // handled below by loop (ROWS*BG == 512 > THREADS)
        for (int idx = tid; idx < ROWS * BG; idx += THREADS) {
            int nn_ = idx >> 3, bb_ = idx & 7;
            states[(size_t)(n0 + nn_) * TB + b0 + bb_] = y_init[n0 + nn_];
        }
        (void)n; (void)b;
    }
    if (ns == 0) {
        for (int idx = tid; idx < NOUT * TS * BG; idx += THREADS) {
            int o   = idx / (TS * BG);
            int rem = idx - o * TS * BG;
            int t = rem >> 3;
            int b = rem & 7;
            outs[(size_t)o * TB + (size_t)t * NB + b0 + b] = 0.f;
        }
    }
    __syncthreads();
    cluster_arrive_();

    // ---- Prefetch: x(1) and rnoise(0) under the cluster barrier ----
    float x_v = 0.f, rn0, rn1;
    if (xload) {
        size_t off = (size_t)xi * TB + (size_t)1 * NB + b0 + xb;
        x_v = __ldcs(u + off) + __ldcs(inoise + off);
    }
    rn0 = __ldcs(rnoise + (size_t)(n0 + n_r0) * TB + b0 + b_r);
    rn1 = __ldcs(rnoise + (size_t)(n0 + n_r1) * TB + b0 + b_r);

    cluster_wait_();   // buf0 seeds + mbar inits + outs zero visible

    // ---- t = 0 outputs ----
    {
        float s0v = y_init[n0 + n_r0];
        float s1v = y_init[n0 + n_r1];
        float v0 = wo0a * s0v + wo0b * s1v;
        float v1 = wo1a * s0v + wo1b * s1v;
        v0 += __shfl_xor_sync(0xffffffffu, v0, 8);
        v0 += __shfl_xor_sync(0xffffffffu, v0, 16);
        v1 += __shfl_xor_sync(0xffffffffu, v1, 8);
        v1 += __shfl_xor_sync(0xffffffffu, v1, 16);
        if (lane < 8) {
            atomicAdd(outs + b0 + lane, v0);
            atomicAdd(outs + TB + b0 + lane, v1);
        }
    }

    int ph0 = 0, ph1 = 0;

    for (int t = 0; t < TS - 1; ++t) {
        // ---- 1. wait for state t (remote + self st.asyncs all tx-counted) ----
        if (t > 0) {
            if (t & 1) { mbar_wait_cluster(mbarbase + 8, ph1); ph1 ^= 1; }
            else       { mbar_wait_cluster(mbarbase, ph0);     ph0 ^= 1; }
        }
        // arm next phase's tx expectation (phase became current at step t-1)
        if (tid == 0 && t < TS - 2)
            mbar_expect_tx(mbarbase + 8 * ((t + 1) & 1), TXB);

        const float* sb = sm + (t & 1) * F_BUF;
        const float* sp = sb + kb * BG;
        const float* sextp = sb + (NN + seg) * BG;

        // ---- 2. GEMM partials: 32 k's (regs W) x 4 rows x 8 batches ----
        ull a00 = 0, a01 = 0, a02 = 0, a03 = 0;
        ull a10 = 0, a11 = 0, a12 = 0, a13 = 0;
        ull a20 = 0, a21 = 0, a22 = 0, a23 = 0;
        ull a30 = 0, a31 = 0, a32 = 0, a33 = 0;
        {
            #pragma unroll
            for (int q = 0; q < 8; ++q) {
                float4 w0q = wr0[q], w1q = wr1[q], w2q = wr2[q], w3q = wr3[q];
                #pragma unroll
                for (int c = 0; c < 4; ++c) {
                    ulonglong2 sA = *(const ulonglong2*)(sp);
                    ulonglong2 sB = *(const ulonglong2*)(sp + 4);
                    float w0v = (c == 0) ? w0q.x : (c == 1) ? w0q.y : (c == 2) ? w0q.z : w0q.w;
                    float w1v = (c == 0) ? w1q.x : (c == 1) ? w1q.y : (c == 2) ? w1q.z : w1q.w;
                    float w2v = (c == 0) ? w2q.x : (c == 1) ? w2q.y : (c == 2) ? w2q.z : w2q.w;
                    float w3v = (c == 0) ? w3q.x : (c == 1) ? w3q.y : (c == 2) ? w3q.z : w3q.w;
                    QFMA(a0, w0v, sA, sB);
                    QFMA(a1, w1v, sA, sB);
                    QFMA(a2, w2v, sA, sB);
                    QFMA(a3, w3v, sA, sB);
                    sp += BG;
                }
            }
            if (seg < NIN) {
                ulonglong2 sA = *(const ulonglong2*)(sextp);
                ulonglong2 sB = *(const ulonglong2*)(sextp + 4);
                QFMA(a0, wi0, sA, sB);
                QFMA(a1, wi1, sA, sB);
                QFMA(a2, wi2, sA, sB);
                QFMA(a3, wi3, sA, sB);
            }
        }
        // ---- 3. store partials ----
        {
            float4 q;
            float* pb = part + (seg * ROWS) * BP;
            unpack2(a00, q.x, q.y); unpack2(a01, q.z, q.w);
            *(float4*)(pb + r0 * BP) = q;
            unpack2(a02, q.x, q.y); unpack2(a03, q.z, q.w);
            *(float4*)(pb + r0 * BP + 4) = q;
            unpack2(a10, q.x, q.y); unpack2(a11, q.z, q.w);
            *(float4*)(pb + r1 * BP) = q;
            unpack2(a12, q.x, q.y); unpack2(a13, q.z, q.w);
            *(float4*)(pb + r1 * BP + 4) = q;
            unpack2(a20, q.x, q.y); unpack2(a21, q.z, q.w);
            *(float4*)(pb + r2 * BP) = q;
            unpack2(a22, q.x, q.y); unpack2(a23, q.z, q.w);
            *(float4*)(pb + r2 * BP + 4) = q;
            unpack2(a30, q.x, q.y); unpack2(a31, q.z, q.w);
            *(float4*)(pb + r3 * BP) = q;
            unpack2(a32, q.x, q.y); unpack2(a33, q.z, q.w);
            *(float4*)(pb + r3 * BP + 4) = q;
        }
        __syncthreads();   // the ONE intra-step barrier (partials ready)

        // ---- 4. reduce, tanh, state update ----
        float ns0, ns1;
        {
            float pre0 = 0.f, pre1 = 0.f;
            #pragma unroll
            for (int s_ = 0; s_ < NSEG; ++s_) {
                pre0 += part[(s_ * ROWS + n_r0) * BP + b_r];
                pre1 += part[(s_ * ROWS + n_r1) * BP + b_r];
            }
            float s0 = sb[(n0 + n_r0) * BG + b_r];
            float s1 = sb[(n0 + n_r1) * BG + b_r];
            ns0 = 0.9f * s0 + 0.1f * (tanh_fast(pre0) + rn0);
            ns1 = 0.9f * s1 + 0.1f * (tanh_fast(pre1) + rn1);
        }

        // ---- 5. DSMEM push: b64 pair to every rank (tx-counted) ----
        // Safety: peers can only overwrite buf[t&1] (as buf[(t+2)&1]) after
        // their step-t+1 wait, which needs ALL our st.asyncs below — and each
        // thread emits only after its own reads of buf[t&1]/part. The single
        // syncthreads above guarantees all GEMM reads of buf[t&1] precede any
        // thread's emit.
        if (t < TS - 2) {
            float p0 = __shfl_xor_sync(0xffffffffu, ns0, 1);
            float p1 = __shfl_xor_sync(0xffffffffu, ns1, 1);
            ull v64 = evenl ? packpair(ns0, p0) : packpair(p1, ns1);
            uint32_t boff = ((t + 1) & 1) ? BUF_BYTES : 0u;
            uint32_t moff = 8u * ((t + 1) & 1);
            uint32_t doff = boff + emit_off;
            #pragma unroll
            for (int r = 0; r < NSL; ++r)
                st_async_b64(pbuf[r] + doff, v64, pmbar[r] + moff);
            if (xload)   // x(t+1) into own buf (tracked by own mbar)
                st_async_b32(pbuf_self + boff + x_off, x_v, pmbar_self + moff);
        }

        // ---- 6. off-chain: states STG, outs RED, next prefetches ----
        {
            size_t so = (size_t)(t + 1) * NB + b0 + b_r;
            states[(size_t)(n0 + n_r0) * TB + so] = ns0;
            states[(size_t)(n0 + n_r1) * TB + so] = ns1;

            float v0 = wo0a * ns0 + wo0b * ns1;
            float v1 = wo1a * ns0 + wo1b * ns1;
            v0 += __shfl_xor_sync(0xffffffffu, v0, 8);
            v0 += __shfl_xor_sync(0xffffffffu, v0, 16);
            v1 += __shfl_xor_sync(0xffffffffu, v1, 8);
            v1 += __shfl_xor_sync(0xffffffffu, v1, 16);
            if (lane < 8) {
                size_t oc = (size_t)(t + 1) * NB + b0 + lane;
                atomicAdd(outs + oc, v0);
                atomicAdd(outs + TB + oc, v1);
            }
        }
        if (t + 1 < TS - 1) {
            size_t toff = (size_t)(t + 1) * NB + b0;
            rn0 = __ldcs(rnoise + (size_t)(n0 + n_r0) * TB + toff + b_r);
            rn1 = __ldcs(rnoise + (size_t)(n0 + n_r1) * TB + toff + b_r);
        }
        if (xload && t + 2 <= TS - 2) {   // x two steps ahead (sent next step)
            size_t off = (size_t)xi * TB + (size_t)(t + 2) * NB + b0 + xb;
            x_v = __ldcs(u + off) + __ldcs(inoise + off);
        }
    }

    // keep cluster SMEM alive until all peers drained (cheap, once)
    cluster_arrive_();
    cluster_wait_();
}

extern "C" void kernel_launch(void* const* d_in, const int* in_sizes, int n_in,
                              void* d_out, int out_size)
{
    const float* u      = (const float*)d_in[0];
    const float* Wrec   = (const float*)d_in[1];
    const float* Winp   = (const float*)d_in[2];
    const float* Wout   = (const float*)d_in[3];
    const float* y_init = (const float*)d_in[4];
    const float* rnoise = (const float*)d_in[5];
    const float* inoise = (const float*)d_in[6];

    float* states = (float*)d_out;
    float* outs   = states + (size_t)NN * TB;

    cudaFuncSetAttribute(rnn_step_kernel,
                         cudaFuncAttributeMaxDynamicSharedMemorySize, SMEM_BYTES);

    dim3 grid(NSL, NBG, 1);
    rnn_step_kernel<<<grid, THREADS, SMEM_BYTES>>>(u, Wrec, Winp, Wout, y_init,
                                                   rnoise, inoise, states, outs);
}

// round 13
// speedup vs baseline: 1.1812x; 1.0146x over previous
#include <cuda_runtime.h>
#include <cstdint>

// Problem constants
#define NN   512
#define NIN  6
#define NOUT 2
#define TS   1200
#define NB   128
#define TB   (TS * NB)          // 153600

// Decomposition: 16 batch-groups x (cluster of 8 n-slice CTAs) = 128 CTAs
#define NSL     8               // n-slices (cluster size)
#define ROWS    64              // rows of W_rec per CTA
#define NBG     16              // batch groups
#define BG      8               // batch per group
#define THREADS 256
#define NSEG    16              // k-segments (8 warps x 2 half-warps)
#define BP      12              // partials row pad (floats, mult of 4 for STS.128)

#define F_BUF   ((NN + NIN + 2) * BG)   // 4160 floats per state buffer
#define BUF_BYTES (F_BUF * 4)           // 16640
#define F_PART  (NSEG * ROWS * BP)      // 12288
#define F_STG   (2 * ROWS * BG)         // 1024: double-buffered 2KB staging slices
#define SLICE_BYTES (ROWS * BG * 4)     // 2048
#define F_MBAR  4                       // 2 x 8-byte mbarriers
#define SMEM_FLOATS (2 * F_BUF + F_PART + F_STG + F_MBAR)
#define SMEM_BYTES  (SMEM_FLOATS * 4)   // 86608 B

// tx bytes per exchange phase: 8 bulk copies x 2048 B + 48 x 4 B (x rows)
#define TXB (NSL * SLICE_BYTES + NIN * BG * 4)   // 16576

typedef unsigned long long ull;

__device__ __forceinline__ ull pack2(float x) {
    ull r;
    unsigned int v = __float_as_uint(x);
    asm("mov.b64 %0, {%1, %1};" : "=l"(r) : "r"(v));
    return r;
}
__device__ __forceinline__ void fma2(ull& d, ull a, ull b) {
    asm("fma.rn.f32x2 %0, %1, %2, %0;" : "+l"(d) : "l"(a), "l"(b));
}
__device__ __forceinline__ void unpack2(ull v, float& lo, float& hi) {
    unsigned int l, h;
    asm("mov.b64 {%0, %1}, %2;" : "=r"(l), "=r"(h) : "l"(v));
    lo = __uint_as_float(l);
    hi = __uint_as_float(h);
}
__device__ __forceinline__ float tanh_fast(float x) {
    float r;
    asm("tanh.approx.f32 %0, %1;" : "=f"(r) : "f"(x));
    return r;
}
__device__ __forceinline__ uint32_t smem_u32(const void* p) {
    uint32_t a;
    asm("{ .reg .u64 t; cvta.to.shared.u64 t, %1; cvt.u32.u64 %0, t; }"
        : "=r"(a) : "l"(p));
    return a;
}
__device__ __forceinline__ uint32_t mapa_rank(uint32_t addr, uint32_t rank) {
    uint32_t r;
    asm("mapa.shared::cluster.u32 %0, %1, %2;" : "=r"(r) : "r"(addr), "r"(rank));
    return r;
}
__device__ __forceinline__ void mbar_init(uint32_t addr, uint32_t cnt) {
    asm volatile("mbarrier.init.shared.b64 [%0], %1;" :: "r"(addr), "r"(cnt) : "memory");
}
__device__ __forceinline__ void mbar_expect_tx(uint32_t addr, uint32_t bytes) {
    asm volatile("mbarrier.arrive.expect_tx.shared.b64 _, [%0], %1;"
                 :: "r"(addr), "r"(bytes) : "memory");
}
// Bulk DSMEM copy: src in local SMEM -> dst in (possibly remote) cluster SMEM,
// completion tx-counted on the destination CTA's mbarrier.
__device__ __forceinline__ void bulk_copy_cluster(uint32_t dst, uint32_t src,
                                                  uint32_t bytes, uint32_t mbar) {
    asm volatile(
        "cp.async.bulk.shared::cluster.shared::cta.mbarrier::complete_tx::bytes "
        "[%0], [%1], %2, [%3];"
        :: "r"(dst), "r"(src), "r"(bytes), "r"(mbar) : "memory");
}
__device__ __forceinline__ void st_async_b32(uint32_t daddr, float v, uint32_t mbar) {
    asm volatile("st.async.shared::cluster.mbarrier::complete_tx::bytes.b32 [%0], %1, [%2];"
                 :: "r"(daddr), "f"(v), "r"(mbar) : "memory");
}
__device__ __forceinline__ void mbar_wait_cluster(uint32_t mbar, uint32_t par) {
    uint32_t done;
    asm volatile(
        "{\n\t"
        ".reg .pred p;\n\t"
        "mbarrier.try_wait.parity.acquire.cluster.shared::cta.b64 p, [%1], %2;\n\t"
        "selp.b32 %0, 1, 0, p;\n\t"
        "}"
        : "=r"(done) : "r"(mbar), "r"(par) : "memory");
    if (!done) {
        asm volatile(
            "{\n\t"
            ".reg .pred P1;\n\t"
            "WL_%=:\n\t"
            "mbarrier.try_wait.parity.acquire.cluster.shared::cta.b64 P1, [%0], %1, 0x989680;\n\t"
            "@P1 bra.uni WD_%=;\n\t"
            "bra.uni WL_%=;\n\t"
            "WD_%=:\n\t"
            "}"
            :: "r"(mbar), "r"(par) : "memory");
    }
}
__device__ __forceinline__ void cluster_arrive_() {
    asm volatile("barrier.cluster.arrive.aligned;" ::: "memory");
}
__device__ __forceinline__ void cluster_wait_() {
    asm volatile("barrier.cluster.wait.aligned;" ::: "memory");
}

#define QFMA(ar, wv, sA, sB)                 \
    do {                                      \
        ull _w = pack2(wv);                   \
        fma2(ar##0, _w, sA.x);                \
        fma2(ar##1, _w, sA.y);                \
        fma2(ar##2, _w, sB.x);                \
        fma2(ar##3, _w, sB.y);                \
    } while (0)

extern "C" __global__ void __cluster_dims__(NSL, 1, 1) __launch_bounds__(THREADS, 1)
rnn_step_kernel(const float* __restrict__ u,
                const float* __restrict__ Wrec,
                const float* __restrict__ Winp,
                const float* __restrict__ Wout,
                const float* __restrict__ y_init,
                const float* __restrict__ rnoise,
                const float* __restrict__ inoise,
                float* __restrict__ states,
                float* __restrict__ outs)
{
    extern __shared__ float sm[];
    // sm: buf0 [520][8] | buf1 [520][8] | part [16][64][12] | stg [2][64][8] | 2 mbars
    float* part = sm + 2 * F_BUF;
    float* stg  = part + F_PART;
    const uint32_t bufbase  = smem_u32(sm);
    const uint32_t stgbase  = smem_u32(stg);
    const uint32_t mbarbase = smem_u32(stg + F_STG);

    const int tid  = threadIdx.x;
    const int ns   = blockIdx.x;     // cluster rank / n-slice
    const int bg   = blockIdx.y;     // batch group
    const int n0   = ns * ROWS;
    const int b0   = bg * BG;
    const int lane = tid & 31;
    const int wid  = tid >> 5;       // 0..7
    const int g    = lane & 15;      // row group: rows {2g,2g+1,2g+32,2g+33}
    const int h    = lane >> 4;      // k half within warp's 64-k segment
    const int seg  = wid * 2 + h;    // 0..15
    const int kb   = wid * 64 + h * 32;

    const int r0 = 2 * g, r1 = 2 * g + 1, r2 = 2 * g + 32, r3 = 2 * g + 33;

    // ---- peer addresses ----
    uint32_t pbuf[NSL], pmbar[NSL];
    #pragma unroll
    for (int r = 0; r < NSL; ++r) {
        pbuf[r]  = mapa_rank(bufbase, r);
        pmbar[r] = mapa_rank(mbarbase, r);
    }
    const uint32_t pbuf_self  = mapa_rank(bufbase, ns);
    const uint32_t pmbar_self = mapa_rank(mbarbase, ns);

    // ---- W_rec slice into registers: 4 rows x 32 k = 32 float4 ----
    float4 wr0[8], wr1[8], wr2[8], wr3[8];
    {
        const float* p0 = Wrec + (size_t)(n0 + r0) * NN + kb;
        const float* p1 = Wrec + (size_t)(n0 + r1) * NN + kb;
        const float* p2 = Wrec + (size_t)(n0 + r2) * NN + kb;
        const float* p3 = Wrec + (size_t)(n0 + r3) * NN + kb;
        #pragma unroll
        for (int q = 0; q < 8; ++q) {
            wr0[q] = *(const float4*)(p0 + 4 * q);
            wr1[q] = *(const float4*)(p1 + 4 * q);
            wr2[q] = *(const float4*)(p2 + 4 * q);
            wr3[q] = *(const float4*)(p3 + 4 * q);
        }
    }
    float wi0 = 0.f, wi1 = 0.f, wi2 = 0.f, wi3 = 0.f;
    if (seg < NIN) {
        wi0 = Winp[(size_t)(n0 + r0) * NIN + seg];
        wi1 = Winp[(size_t)(n0 + r1) * NIN + seg];
        wi2 = Winp[(size_t)(n0 + r2) * NIN + seg];
        wi3 = Winp[(size_t)(n0 + r3) * NIN + seg];
    }

    // Reducer output assignments (2 outputs per thread)
    const int n_r0 = tid >> 3;            // 0..31
    const int n_r1 = (tid + 256) >> 3;    // 32..63
    const int b_r  = tid & 7;
    const float wo0a = Wout[n0 + n_r0];
    const float wo0b = Wout[n0 + n_r1];
    const float wo1a = Wout[NN + n0 + n_r0];
    const float wo1b = Wout[NN + n0 + n_r1];

    // x loader assignment (threads 0..47)
    const bool xload = (tid < NIN * BG);
    const int  xi = tid >> 3, xb = tid & 7;
    const uint32_t x_off = (uint32_t)((NN + xi) * BG + xb) * 4;

    // ---- mbarrier init; count=1 (thread0's expect_tx arrive per phase) ----
    if (tid == 0) {
        mbar_init(mbarbase, 1);
        mbar_init(mbarbase + 8, 1);
    }

    // ---- Seed buf0 with full y_init state, x(0), states/outs ----
    for (int idx = tid; idx < NN * BG; idx += THREADS)
        sm[idx] = y_init[idx >> 3];
    if (xload) {
        size_t off = (size_t)xi * TB + b0 + xb;
        sm[(NN + xi) * BG + xb] = __ldcs(u + off) + __ldcs(inoise + off);
    }
    for (int idx = tid; idx < ROWS * BG; idx += THREADS) {
        int nn_ = idx >> 3, bb_ = idx & 7;
        states[(size_t)(n0 + nn_) * TB + b0 + bb_] = y_init[n0 + nn_];
    }
    if (ns == 0) {
        for (int idx = tid; idx < NOUT * TS * BG; idx += THREADS) {
            int o   = idx / (TS * BG);
            int rem = idx - o * TS * BG;
            int t = rem >> 3;
            int b = rem & 7;
            outs[(size_t)o * TB + (size_t)t * NB + b0 + b] = 0.f;
        }
    }
    __syncthreads();
    cluster_arrive_();

    // ---- Prefetch: x(1) and rnoise(0) under the cluster barrier ----
    float x_v = 0.f, rn0, rn1;
    if (xload) {
        size_t off = (size_t)xi * TB + (size_t)1 * NB + b0 + xb;
        x_v = __ldcs(u + off) + __ldcs(inoise + off);
    }
    rn0 = __ldcs(rnoise + (size_t)(n0 + n_r0) * TB + b0 + b_r);
    rn1 = __ldcs(rnoise + (size_t)(n0 + n_r1) * TB + b0 + b_r);

    cluster_wait_();   // buf0 seeds + mbar inits + outs zero visible

    // ---- t = 0 outputs ----
    {
        float s0v = y_init[n0 + n_r0];
        float s1v = y_init[n0 + n_r1];
        float v0 = wo0a * s0v + wo0b * s1v;
        float v1 = wo1a * s0v + wo1b * s1v;
        v0 += __shfl_xor_sync(0xffffffffu, v0, 8);
        v0 += __shfl_xor_sync(0xffffffffu, v0, 16);
        v1 += __shfl_xor_sync(0xffffffffu, v1, 8);
        v1 += __shfl_xor_sync(0xffffffffu, v1, 16);
        if (lane < 8) {
            atomicAdd(outs + b0 + lane, v0);
            atomicAdd(outs + TB + b0 + lane, v1);
        }
    }

    int ph0 = 0, ph1 = 0;

    for (int t = 0; t < TS - 1; ++t) {
        // ---- 1. wait for state t (all 8 bulk copies + self x msgs counted) ----
        if (t > 0) {
            if (t & 1) { mbar_wait_cluster(mbarbase + 8, ph1); ph1 ^= 1; }
            else       { mbar_wait_cluster(mbarbase, ph0);     ph0 ^= 1; }
        }
        if (tid == 0 && t < TS - 2)
            mbar_expect_tx(mbarbase + 8 * ((t + 1) & 1), TXB);

        const float* sb = sm + (t & 1) * F_BUF;
        const float* sp = sb + kb * BG;
        const float* sextp = sb + (NN + seg) * BG;

        // ---- 2. GEMM partials: 32 k's (regs W) x 4 rows x 8 batches ----
        ull a00 = 0, a01 = 0, a02 = 0, a03 = 0;
        ull a10 = 0, a11 = 0, a12 = 0, a13 = 0;
        ull a20 = 0, a21 = 0, a22 = 0, a23 = 0;
        ull a30 = 0, a31 = 0, a32 = 0, a33 = 0;
        {
            #pragma unroll
            for (int q = 0; q < 8; ++q) {
                float4 w0q = wr0[q], w1q = wr1[q], w2q = wr2[q], w3q = wr3[q];
                #pragma unroll
                for (int c = 0; c < 4; ++c) {
                    ulonglong2 sA = *(const ulonglong2*)(sp);
                    ulonglong2 sB = *(const ulonglong2*)(sp + 4);
                    float w0v = (c == 0) ? w0q.x : (c == 1) ? w0q.y : (c == 2) ? w0q.z : w0q.w;
                    float w1v = (c == 0) ? w1q.x : (c == 1) ? w1q.y : (c == 2) ? w1q.z : w1q.w;
                    float w2v = (c == 0) ? w2q.x : (c == 1) ? w2q.y : (c == 2) ? w2q.z : w2q.w;
                    float w3v = (c == 0) ? w3q.x : (c == 1) ? w3q.y : (c == 2) ? w3q.z : w3q.w;
                    QFMA(a0, w0v, sA, sB);
                    QFMA(a1, w1v, sA, sB);
                    QFMA(a2, w2v, sA, sB);
                    QFMA(a3, w3v, sA, sB);
                    sp += BG;
                }
            }
            if (seg < NIN) {
                ulonglong2 sA = *(const ulonglong2*)(sextp);
                ulonglong2 sB = *(const ulonglong2*)(sextp + 4);
                QFMA(a0, wi0, sA, sB);
                QFMA(a1, wi1, sA, sB);
                QFMA(a2, wi2, sA, sB);
                QFMA(a3, wi3, sA, sB);
            }
        }
        // ---- 3. store partials ----
        {
            float4 q;
            float* pb = part + (seg * ROWS) * BP;
            unpack2(a00, q.x, q.y); unpack2(a01, q.z, q.w);
            *(float4*)(pb + r0 * BP) = q;
            unpack2(a02, q.x, q.y); unpack2(a03, q.z, q.w);
            *(float4*)(pb + r0 * BP + 4) = q;
            unpack2(a10, q.x, q.y); unpack2(a11, q.z, q.w);
            *(float4*)(pb + r1 * BP) = q;
            unpack2(a12, q.x, q.y); unpack2(a13, q.z, q.w);
            *(float4*)(pb + r1 * BP + 4) = q;
            unpack2(a20, q.x, q.y); unpack2(a21, q.z, q.w);
            *(float4*)(pb + r2 * BP) = q;
            unpack2(a22, q.x, q.y); unpack2(a23, q.z, q.w);
            *(float4*)(pb + r2 * BP + 4) = q;
            unpack2(a30, q.x, q.y); unpack2(a31, q.z, q.w);
            *(float4*)(pb + r3 * BP) = q;
            unpack2(a32, q.x, q.y); unpack2(a33, q.z, q.w);
            *(float4*)(pb + r3 * BP + 4) = q;
        }
        __syncthreads();   // partials ready

        // ---- 4. reduce, tanh, state update -> STAGING slice ----
        float ns0, ns1;
        const int p = (t + 1) & 1;
        {
            float pre0 = 0.f, pre1 = 0.f;
            #pragma unroll
            for (int s_ = 0; s_ < NSEG; ++s_) {
                pre0 += part[(s_ * ROWS + n_r0) * BP + b_r];
                pre1 += part[(s_ * ROWS + n_r1) * BP + b_r];
            }
            float s0 = sb[(n0 + n_r0) * BG + b_r];
            float s1 = sb[(n0 + n_r1) * BG + b_r];
            ns0 = 0.9f * s0 + 0.1f * (tanh_fast(pre0) + rn0);
            ns1 = 0.9f * s1 + 0.1f * (tanh_fast(pre1) + rn1);
            // staging: local slice [64][8]; writes are contiguous per thread
            stg[p * (ROWS * BG) + n_r0 * BG + b_r] = ns0;
            stg[p * (ROWS * BG) + n_r1 * BG + b_r] = ns1;
        }
        // x(t+1) push (tx-counted self msg). Safe after wait-t: mbar-t firing
        // implies all step-(t-1) readers of buf[(t+1)&1] finished cluster-wide.
        if (xload && t < TS - 2)
            st_async_b32(pbuf_self + (uint32_t)p * BUF_BYTES + x_off, x_v,
                         pmbar_self + 8u * p);
        __syncthreads();   // staging slice complete

        // ---- 5. bulk push: ONE 2KB copy per rank (incl. self), tx-counted ----
        // Staging double-buffer safety: copies issued at step t read stg[p];
        // stg[p] is next overwritten at step t+2. Our wait-(t+2) needs peer r's
        // step-(t+1) push, which needs r's wait-(t+1), which needs THIS copy's
        // completion — so the copy has drained before stg[p] is rewritten.
        if (tid == 0 && t < TS - 2) {
            uint32_t src  = stgbase + (uint32_t)p * SLICE_BYTES;
            uint32_t doff = (uint32_t)p * BUF_BYTES + (uint32_t)(n0 * BG) * 4;
            #pragma unroll
            for (int r = 0; r < NSL; ++r)
                bulk_copy_cluster(pbuf[r] + doff, src, SLICE_BYTES,
                                  pmbar[r] + 8u * p);
        }

        // ---- 6. off-chain: states STG, outs RED, next prefetches ----
        {
            size_t so = (size_t)(t + 1) * NB + b0 + b_r;
            states[(size_t)(n0 + n_r0) * TB + so] = ns0;
            states[(size_t)(n0 + n_r1) * TB + so] = ns1;

            float v0 = wo0a * ns0 + wo0b * ns1;
            float v1 = wo1a * ns0 + wo1b * ns1;
            v0 += __shfl_xor_sync(0xffffffffu, v0, 8);
            v0 += __shfl_xor_sync(0xffffffffu, v0, 16);
            v1 += __shfl_xor_sync(0xffffffffu, v1, 8);
            v1 += __shfl_xor_sync(0xffffffffu, v1, 16);
            if (lane < 8) {
                size_t oc = (size_t)(t + 1) * NB + b0 + lane;
                atomicAdd(outs + oc, v0);
                atomicAdd(outs + TB + oc, v1);
            }
        }
        if (t + 1 < TS - 1) {
            size_t toff = (size_t)(t + 1) * NB + b0;
            rn0 = __ldcs(rnoise + (size_t)(n0 + n_r0) * TB + toff + b_r);
            rn1 = __ldcs(rnoise + (size_t)(n0 + n_r1) * TB + toff + b_r);
        }
        if (xload && t + 2 <= TS - 2) {
            size_t off = (size_t)xi * TB + (size_t)(t + 2) * NB + b0 + xb;
            x_v = __ldcs(u + off) + __ldcs(inoise + off);
        }
    }

    // keep cluster SMEM alive until all peers drained
    cluster_arrive_();
    cluster_wait_();
}

extern "C" void kernel_launch(void* const* d_in, const int* in_sizes, int n_in,
                              void* d_out, int out_size)
{
    const float* u      = (const float*)d_in[0];
    const float* Wrec   = (const float*)d_in[1];
    const float* Winp   = (const float*)d_in[2];
    const float* Wout   = (const float*)d_in[3];
    const float* y_init = (const float*)d_in[4];
    const float* rnoise = (const float*)d_in[5];
    const float* inoise = (const float*)d_in[6];

    float* states = (float*)d_out;
    float* outs   = states + (size_t)NN * TB;

    cudaFuncSetAttribute(rnn_step_kernel,
                         cudaFuncAttributeMaxDynamicSharedMemorySize, SMEM_BYTES);

    dim3 grid(NSL, NBG, 1);
    rnn_step_kernel<<<grid, THREADS, SMEM_BYTES>>>(u, Wrec, Winp, Wout, y_init,
                                                   rnoise, inoise, states, outs);
}

// round 14
// speedup vs baseline: 1.3658x; 1.1563x over previous
#include <cuda_runtime.h>
#include <cstdint>

// Problem constants
#define NN   512
#define NIN  6
#define NOUT 2
#define TS   1200
#define NB   128
#define TB   (TS * NB)          // 153600

// Decomposition: 8 cluster-groups x (cluster of 8 n-slice CTAs) = 64 CTAs.
// Each cluster time-interleaves TWO independent batch-group chains (A/B) so
// each chain's DSMEM exchange latency hides under the other's compute.
#define NSL     8               // n-slices (cluster size)
#define ROWS    64              // rows of W_rec per CTA
#define NCH     2               // chains (batch-groups) per cluster
#define NBG     16              // total batch groups
#define BG      8               // batch per group
#define THREADS 256
#define NSEG    16              // k-segments (8 warps x 2 half-warps)
#define BP      12              // partials row pad (floats, mult of 4)

#define F_BUF   ((NN + NIN + 2) * BG)   // 4160 floats per state buffer
#define BUF_BYTES (F_BUF * 4)           // 16640
#define F_PART  (NSEG * ROWS * BP)      // 12288 (shared across chains)
#define SLICE   (ROWS * BG)             // 512 floats
#define SLICE_BYTES (SLICE * 4)         // 2048
#define F_STG   (NCH * 2 * SLICE)       // 2048: [chain][phase] staging
#define F_MBAR  8                       // 4 x 8-byte mbarriers
#define SMEM_FLOATS (NCH * 2 * F_BUF + F_PART + F_STG + F_MBAR)
#define SMEM_BYTES  (SMEM_FLOATS * 4)   // 123,936 B < 227 KB

// tx bytes per chain-phase: 8 bulk copies x 2048 B + 48 x 4 B (x rows)
#define TXB (NSL * SLICE_BYTES + NIN * BG * 4)   // 16576

typedef unsigned long long ull;

__device__ __forceinline__ ull pack2(float x) {
    ull r;
    unsigned int v = __float_as_uint(x);
    asm("mov.b64 %0, {%1, %1};" : "=l"(r) : "r"(v));
    return r;
}
__device__ __forceinline__ void fma2(ull& d, ull a, ull b) {
    asm("fma.rn.f32x2 %0, %1, %2, %0;" : "+l"(d) : "l"(a), "l"(b));
}
__device__ __forceinline__ void unpack2(ull v, float& lo, float& hi) {
    unsigned int l, h;
    asm("mov.b64 {%0, %1}, %2;" : "=r"(l), "=r"(h) : "l"(v));
    lo = __uint_as_float(l);
    hi = __uint_as_float(h);
}
__device__ __forceinline__ float tanh_fast(float x) {
    float r;
    asm("tanh.approx.f32 %0, %1;" : "=f"(r) : "f"(x));
    return r;
}
__device__ __forceinline__ uint32_t smem_u32(const void* p) {
    uint32_t a;
    asm("{ .reg .u64 t; cvta.to.shared.u64 t, %1; cvt.u32.u64 %0, t; }"
        : "=r"(a) : "l"(p));
    return a;
}
__device__ __forceinline__ uint32_t mapa_rank(uint32_t addr, uint32_t rank) {
    uint32_t r;
    asm("mapa.shared::cluster.u32 %0, %1, %2;" : "=r"(r) : "r"(addr), "r"(rank));
    return r;
}
__device__ __forceinline__ void mbar_init(uint32_t addr, uint32_t cnt) {
    asm volatile("mbarrier.init.shared.b64 [%0], %1;" :: "r"(addr), "r"(cnt) : "memory");
}
__device__ __forceinline__ void mbar_expect_tx(uint32_t addr, uint32_t bytes) {
    asm volatile("mbarrier.arrive.expect_tx.shared.b64 _, [%0], %1;"
                 :: "r"(addr), "r"(bytes) : "memory");
}
__device__ __forceinline__ void bulk_copy_cluster(uint32_t dst, uint32_t src,
                                                  uint32_t bytes, uint32_t mbar) {
    asm volatile(
        "cp.async.bulk.shared::cluster.shared::cta.mbarrier::complete_tx::bytes "
        "[%0], [%1], %2, [%3];"
        :: "r"(dst), "r"(src), "r"(bytes), "r"(mbar) : "memory");
}
__device__ __forceinline__ void st_async_b32(uint32_t daddr, float v, uint32_t mbar) {
    asm volatile("st.async.shared::cluster.mbarrier::complete_tx::bytes.b32 [%0], %1, [%2];"
                 :: "r"(daddr), "f"(v), "r"(mbar) : "memory");
}
__device__ __forceinline__ void mbar_wait_cluster(uint32_t mbar, uint32_t par) {
    uint32_t done;
    asm volatile(
        "{\n\t"
        ".reg .pred p;\n\t"
        "mbarrier.try_wait.parity.acquire.cluster.shared::cta.b64 p, [%1], %2;\n\t"
        "selp.b32 %0, 1, 0, p;\n\t"
        "}"
        : "=r"(done) : "r"(mbar), "r"(par) : "memory");
    if (!done) {
        asm volatile(
            "{\n\t"
            ".reg .pred P1;\n\t"
            "WL_%=:\n\t"
            "mbarrier.try_wait.parity.acquire.cluster.shared::cta.b64 P1, [%0], %1, 0x989680;\n\t"
            "@P1 bra.uni WD_%=;\n\t"
            "bra.uni WL_%=;\n\t"
            "WD_%=:\n\t"
            "}"
            :: "r"(mbar), "r"(par) : "memory");
    }
}
__device__ __forceinline__ void cluster_arrive_() {
    asm volatile("barrier.cluster.arrive.aligned;" ::: "memory");
}
__device__ __forceinline__ void cluster_wait_() {
    asm volatile("barrier.cluster.wait.aligned;" ::: "memory");
}

#define QFMA(ar, wv, sA, sB)                 \
    do {                                      \
        ull _w = pack2(wv);                   \
        fma2(ar##0, _w, sA.x);                \
        fma2(ar##1, _w, sA.y);                \
        fma2(ar##2, _w, sB.x);                \
        fma2(ar##3, _w, sB.y);                \
    } while (0)

extern "C" __global__ void __cluster_dims__(NSL, 1, 1) __launch_bounds__(THREADS, 1)
rnn_step_kernel(const float* __restrict__ u,
                const float* __restrict__ Wrec,
                const float* __restrict__ Winp,
                const float* __restrict__ Wout,
                const float* __restrict__ y_init,
                const float* __restrict__ rnoise,
                const float* __restrict__ inoise,
                float* __restrict__ states,
                float* __restrict__ outs)
{
    extern __shared__ float sm[];
    // sm: buf[ch][ph] 4x[520][8] | part [16][64][12] | stg [2][2][512] | 4 mbars
    float* part = sm + NCH * 2 * F_BUF;
    float* stg  = part + F_PART;
    const uint32_t bufbase  = smem_u32(sm);
    const uint32_t stgbase  = smem_u32(stg);
    const uint32_t mbarbase = smem_u32(stg + F_STG);

    const int tid  = threadIdx.x;
    const int ns   = blockIdx.x;     // cluster rank / n-slice
    const int bgc  = blockIdx.y;     // cluster-group 0..7 (owns bgs 2*bgc, 2*bgc+1)
    const int n0   = ns * ROWS;
    const int lane = tid & 31;
    const int wid  = tid >> 5;       // 0..7
    const int g    = lane & 15;
    const int h    = lane >> 4;
    const int seg  = wid * 2 + h;    // 0..15
    const int kb   = wid * 64 + h * 32;

    const int r0 = 2 * g, r1 = 2 * g + 1, r2 = 2 * g + 32, r3 = 2 * g + 33;

    int b0c[NCH];
    #pragma unroll
    for (int c = 0; c < NCH; ++c) b0c[c] = (bgc * NCH + c) * BG;

    // ---- peer addresses ----
    uint32_t pbuf[NSL], pmbar[NSL];
    #pragma unroll
    for (int r = 0; r < NSL; ++r) {
        pbuf[r]  = mapa_rank(bufbase, r);
        pmbar[r] = mapa_rank(mbarbase, r);
    }
    const uint32_t pbuf_self  = mapa_rank(bufbase, ns);
    const uint32_t pmbar_self = mapa_rank(mbarbase, ns);

    // ---- W_rec slice into registers: 4 rows x 32 k = 32 float4 ----
    float4 wr0[8], wr1[8], wr2[8], wr3[8];
    {
        const float* p0 = Wrec + (size_t)(n0 + r0) * NN + kb;
        const float* p1 = Wrec + (size_t)(n0 + r1) * NN + kb;
        const float* p2 = Wrec + (size_t)(n0 + r2) * NN + kb;
        const float* p3 = Wrec + (size_t)(n0 + r3) * NN + kb;
        #pragma unroll
        for (int q = 0; q < 8; ++q) {
            wr0[q] = *(const float4*)(p0 + 4 * q);
            wr1[q] = *(const float4*)(p1 + 4 * q);
            wr2[q] = *(const float4*)(p2 + 4 * q);
            wr3[q] = *(const float4*)(p3 + 4 * q);
        }
    }
    float wi0 = 0.f, wi1 = 0.f, wi2 = 0.f, wi3 = 0.f;
    if (seg < NIN) {
        wi0 = Winp[(size_t)(n0 + r0) * NIN + seg];
        wi1 = Winp[(size_t)(n0 + r1) * NIN + seg];
        wi2 = Winp[(size_t)(n0 + r2) * NIN + seg];
        wi3 = Winp[(size_t)(n0 + r3) * NIN + seg];
    }

    // Reducer output assignments (2 outputs per thread)
    const int n_r0 = tid >> 3;            // 0..31
    const int n_r1 = (tid + 256) >> 3;    // 32..63
    const int b_r  = tid & 7;
    const float wo0a = Wout[n0 + n_r0];
    const float wo0b = Wout[n0 + n_r1];
    const float wo1a = Wout[NN + n0 + n_r0];
    const float wo1b = Wout[NN + n0 + n_r1];

    // x loader assignment (threads 0..47)
    const bool xload = (tid < NIN * BG);
    const int  xi = tid >> 3, xb = tid & 7;
    const uint32_t x_off = (uint32_t)((NN + xi) * BG + xb) * 4;

    // ---- mbarrier init: 4 barriers [chain][phase], count=1 ----
    if (tid == 0) {
        #pragma unroll
        for (int i = 0; i < NCH * 2; ++i)
            mbar_init(mbarbase + 8u * i, 1);
    }

    // ---- Seed both chains' buf[ch][0], x(0), states t=0, zero outs ----
    #pragma unroll
    for (int c = 0; c < NCH; ++c) {
        float* bufc0 = sm + (c * 2) * F_BUF;
        for (int idx = tid; idx < NN * BG; idx += THREADS)
            bufc0[idx] = y_init[idx >> 3];
        if (xload) {
            size_t off = (size_t)xi * TB + b0c[c] + xb;
            bufc0[(NN + xi) * BG + xb] = __ldcs(u + off) + __ldcs(inoise + off);
        }
        for (int idx = tid; idx < ROWS * BG; idx += THREADS) {
            int nn_ = idx >> 3, bb_ = idx & 7;
            states[(size_t)(n0 + nn_) * TB + b0c[c] + bb_] = y_init[n0 + nn_];
        }
        if (ns == 0) {
            for (int idx = tid; idx < NOUT * TS * BG; idx += THREADS) {
                int o   = idx / (TS * BG);
                int rem = idx - o * TS * BG;
                int t = rem >> 3;
                int b = rem & 7;
                outs[(size_t)o * TB + (size_t)t * NB + b0c[c] + b] = 0.f;
            }
        }
    }
    __syncthreads();
    cluster_arrive_();

    // ---- Prefetch per chain: x(1) and rnoise(0) ----
    float x_v[NCH], rn0[NCH], rn1[NCH];
    #pragma unroll
    for (int c = 0; c < NCH; ++c) {
        x_v[c] = 0.f;
        if (xload) {
            size_t off = (size_t)xi * TB + (size_t)1 * NB + b0c[c] + xb;
            x_v[c] = __ldcs(u + off) + __ldcs(inoise + off);
        }
        rn0[c] = __ldcs(rnoise + (size_t)(n0 + n_r0) * TB + b0c[c] + b_r);
        rn1[c] = __ldcs(rnoise + (size_t)(n0 + n_r1) * TB + b0c[c] + b_r);
    }

    cluster_wait_();   // seeds + mbar inits + outs zero visible cluster-wide

    // ---- t = 0 outputs (both chains) ----
    {
        float s0v = y_init[n0 + n_r0];
        float s1v = y_init[n0 + n_r1];
        float v0 = wo0a * s0v + wo0b * s1v;
        float v1 = wo1a * s0v + wo1b * s1v;
        v0 += __shfl_xor_sync(0xffffffffu, v0, 8);
        v0 += __shfl_xor_sync(0xffffffffu, v0, 16);
        v1 += __shfl_xor_sync(0xffffffffu, v1, 8);
        v1 += __shfl_xor_sync(0xffffffffu, v1, 16);
        if (lane < 8) {
            #pragma unroll
            for (int c = 0; c < NCH; ++c) {
                atomicAdd(outs + b0c[c] + lane, v0);
                atomicAdd(outs + TB + b0c[c] + lane, v1);
            }
        }
    }

    int ph[NCH][2] = {{0, 0}, {0, 0}};

    for (int t = 0; t < TS - 1; ++t) {
        const int cur = t & 1;
        const int p   = (t + 1) & 1;
        #pragma unroll
        for (int c = 0; c < NCH; ++c) {
            const uint32_t mcur = 8u * (c * 2 + cur);
            const uint32_t mnxt = 8u * (c * 2 + p);

            // ---- 1. wait chain c state t (hidden under other chain's work) ----
            if (t > 0) {
                mbar_wait_cluster(mbarbase + mcur, ph[c][cur]);
                ph[c][cur] ^= 1;
            }
            if (tid == 0 && t < TS - 2)
                mbar_expect_tx(mbarbase + mnxt, TXB);

            const float* sb = sm + (c * 2 + cur) * F_BUF;
            const float* sp = sb + kb * BG;
            const float* sextp = sb + (NN + seg) * BG;

            // ---- 2. GEMM partials ----
            ull a00 = 0, a01 = 0, a02 = 0, a03 = 0;
            ull a10 = 0, a11 = 0, a12 = 0, a13 = 0;
            ull a20 = 0, a21 = 0, a22 = 0, a23 = 0;
            ull a30 = 0, a31 = 0, a32 = 0, a33 = 0;
            {
                #pragma unroll
                for (int q = 0; q < 8; ++q) {
                    float4 w0q = wr0[q], w1q = wr1[q], w2q = wr2[q], w3q = wr3[q];
                    #pragma unroll
                    for (int cc = 0; cc < 4; ++cc) {
                        ulonglong2 sA = *(const ulonglong2*)(sp);
                        ulonglong2 sB = *(const ulonglong2*)(sp + 4);
                        float w0v = (cc == 0) ? w0q.x : (cc == 1) ? w0q.y : (cc == 2) ? w0q.z : w0q.w;
                        float w1v = (cc == 0) ? w1q.x : (cc == 1) ? w1q.y : (cc == 2) ? w1q.z : w1q.w;
                        float w2v = (cc == 0) ? w2q.x : (cc == 1) ? w2q.y : (cc == 2) ? w2q.z : w2q.w;
                        float w3v = (cc == 0) ? w3q.x : (cc == 1) ? w3q.y : (cc == 2) ? w3q.z : w3q.w;
                        QFMA(a0, w0v, sA, sB);
                        QFMA(a1, w1v, sA, sB);
                        QFMA(a2, w2v, sA, sB);
                        QFMA(a3, w3v, sA, sB);
                        sp += BG;
                    }
                }
                if (seg < NIN) {
                    ulonglong2 sA = *(const ulonglong2*)(sextp);
                    ulonglong2 sB = *(const ulonglong2*)(sextp + 4);
                    QFMA(a0, wi0, sA, sB);
                    QFMA(a1, wi1, sA, sB);
                    QFMA(a2, wi2, sA, sB);
                    QFMA(a3, wi3, sA, sB);
                }
            }
            // ---- 3. store partials ----
            {
                float4 q;
                float* pb = part + (seg * ROWS) * BP;
                unpack2(a00, q.x, q.y); unpack2(a01, q.z, q.w);
                *(float4*)(pb + r0 * BP) = q;
                unpack2(a02, q.x, q.y); unpack2(a03, q.z, q.w);
                *(float4*)(pb + r0 * BP + 4) = q;
                unpack2(a10, q.x, q.y); unpack2(a11, q.z, q.w);
                *(float4*)(pb + r1 * BP) = q;
                unpack2(a12, q.x, q.y); unpack2(a13, q.z, q.w);
                *(float4*)(pb + r1 * BP + 4) = q;
                unpack2(a20, q.x, q.y); unpack2(a21, q.z, q.w);
                *(float4*)(pb + r2 * BP) = q;
                unpack2(a22, q.x, q.y); unpack2(a23, q.z, q.w);
                *(float4*)(pb + r2 * BP + 4) = q;
                unpack2(a30, q.x, q.y); unpack2(a31, q.z, q.w);
                *(float4*)(pb + r3 * BP) = q;
                unpack2(a32, q.x, q.y); unpack2(a33, q.z, q.w);
                *(float4*)(pb + r3 * BP + 4) = q;
            }
            __syncthreads();   // partials ready (also separates chains' use of part)

            // ---- 4. reduce, tanh, update -> staging[c][p] ----
            float ns0, ns1;
            {
                float pre0 = 0.f, pre1 = 0.f;
                #pragma unroll
                for (int s_ = 0; s_ < NSEG; ++s_) {
                    pre0 += part[(s_ * ROWS + n_r0) * BP + b_r];
                    pre1 += part[(s_ * ROWS + n_r1) * BP + b_r];
                }
                float s0 = sb[(n0 + n_r0) * BG + b_r];
                float s1 = sb[(n0 + n_r1) * BG + b_r];
                ns0 = 0.9f * s0 + 0.1f * (tanh_fast(pre0) + rn0[c]);
                ns1 = 0.9f * s1 + 0.1f * (tanh_fast(pre1) + rn1[c]);
                stg[(c * 2 + p) * SLICE + n_r0 * BG + b_r] = ns0;
                stg[(c * 2 + p) * SLICE + n_r1 * BG + b_r] = ns1;
            }
            // x(t+1) push; safe after wait-t (all step-(t-1) readers of the
            // target phase finished cluster-wide before mbar-t fired).
            if (xload && t < TS - 2)
                st_async_b32(pbuf_self + (uint32_t)(c * 2 + p) * BUF_BYTES + x_off,
                             x_v[c], pmbar_self + mnxt);
            __syncthreads();   // staging slice complete

            // ---- 5. bulk push: ONE 2KB copy per rank, tx-counted ----
            // stg[c][p] reuse safety: next overwrite is at step t+2; our
            // wait-(t+2) transitively requires this copy's completion.
            if (tid == 0 && t < TS - 2) {
                uint32_t src  = stgbase + (uint32_t)(c * 2 + p) * SLICE_BYTES;
                uint32_t doff = (uint32_t)(c * 2 + p) * BUF_BYTES
                              + (uint32_t)(n0 * BG) * 4;
                #pragma unroll
                for (int r = 0; r < NSL; ++r)
                    bulk_copy_cluster(pbuf[r] + doff, src, SLICE_BYTES,
                                      pmbar[r] + mnxt);
            }

            // ---- 6. off-chain: states STG, outs RED, next prefetches ----
            {
                size_t so = (size_t)(t + 1) * NB + b0c[c] + b_r;
                states[(size_t)(n0 + n_r0) * TB + so] = ns0;
                states[(size_t)(n0 + n_r1) * TB + so] = ns1;

                float v0 = wo0a * ns0 + wo0b * ns1;
                float v1 = wo1a * ns0 + wo1b * ns1;
                v0 += __shfl_xor_sync(0xffffffffu, v0, 8);
                v0 += __shfl_xor_sync(0xffffffffu, v0, 16);
                v1 += __shfl_xor_sync(0xffffffffu, v1, 8);
                v1 += __shfl_xor_sync(0xffffffffu, v1, 16);
                if (lane < 8) {
                    size_t oc = (size_t)(t + 1) * NB + b0c[c] + lane;
                    atomicAdd(outs + oc, v0);
                    atomicAdd(outs + TB + oc, v1);
                }
            }
            if (t + 1 < TS - 1) {
                size_t toff = (size_t)(t + 1) * NB + b0c[c];
                rn0[c] = __ldcs(rnoise + (size_t)(n0 + n_r0) * TB + toff + b_r);
                rn1[c] = __ldcs(rnoise + (size_t)(n0 + n_r1) * TB + toff + b_r);
            }
            if (xload && t + 2 <= TS - 2) {
                size_t off = (size_t)xi * TB + (size_t)(t + 2) * NB + b0c[c] + xb;
                x_v[c] = __ldcs(u + off) + __ldcs(inoise + off);
            }
        }
    }

    // keep cluster SMEM alive until all peers drained
    cluster_arrive_();
    cluster_wait_();
}

extern "C" void kernel_launch(void* const* d_in, const int* in_sizes, int n_in,
                              void* d_out, int out_size)
{
    const float* u      = (const float*)d_in[0];
    const float* Wrec   = (const float*)d_in[1];
    const float* Winp   = (const float*)d_in[2];
    const float* Wout   = (const float*)d_in[3];
    const float* y_init = (const float*)d_in[4];
    const float* rnoise = (const float*)d_in[5];
    const float* inoise = (const float*)d_in[6];

    float* states = (float*)d_out;
    float* outs   = states + (size_t)NN * TB;

    cudaFuncSetAttribute(rnn_step_kernel,
                         cudaFuncAttributeMaxDynamicSharedMemorySize, SMEM_BYTES);

    dim3 grid(NSL, NBG / NCH, 1);   // 8 x 8 = 64 CTAs
    rnn_step_kernel<<<grid, THREADS, SMEM_BYTES>>>(u, Wrec, Winp, Wout, y_init,
                                                   rnoise, inoise, states, outs);
}